// round 1
// baseline (speedup 1.0000x reference)
#include <cuda_runtime.h>

// PoseNoiseTransform: quaternion prefix-product scan.
//   q:     [TS, NS, 4] float32 unit quaternions (w,x,y,z)
//   noise: [TS-1, NS, 4] float32 uniform [0,1)
//   out:   [TS, NS, 4] float32
//
// out[0]   = q[0]
// q_dot[t] = (q[t+1] * conj(q[t])) * normalize((noise[t]-0.5)*[1,.05,.05,.05])
// out[i+1] = q_dot[i] * q_dot[i-1] * ... * q_dot[0] * q[0]
//
// 3-phase chunked scan over t: chunk totals -> per-column carry scan -> apply.

#define NCH 64          // chunks along time dimension
#define BLK 256         // threads per block (columns per block)
#define NS_MAX 8192     // scratch sized for up to 8192 columns

// Scratch (device globals: no allocations allowed in kernel_launch).
__device__ float4 g_totals[NCH * NS_MAX];  // chunk products   [c][n]
__device__ float4 g_carry [NCH * NS_MAX];  // exclusive carries [c][n] (includes q0)

// Quaternion layout in float4: .x=w .y=x .z=y .w=z
__device__ __forceinline__ float4 qmul(float4 a, float4 b) {
    float aw = a.x, ax = a.y, ay = a.z, az = a.w;
    float bw = b.x, bx = b.y, by = b.z, bz = b.w;
    return make_float4(
        aw * bw - ax * bx - ay * by - az * bz,
        aw * bx + ax * bw + ay * bz - az * by,
        aw * by - ax * bz + ay * bw + az * bx,
        aw * bz + ax * by - ay * bx + az * bw);
}

// q_dot[t] for one (t, n): qnext = q[t+1], qprev = q[t], nz = noise[t]
__device__ __forceinline__ float4 qdot_step(float4 qnext, float4 qprev, float4 nz) {
    // rel = qnext * conj(qprev): fold conj signs directly
    float aw = qnext.x, ax = qnext.y, ay = qnext.z, az = qnext.w;
    float bw = qprev.x, bx = -qprev.y, by = -qprev.z, bz = -qprev.w;
    float4 rel = make_float4(
        aw * bw - ax * bx - ay * by - az * bz,
        aw * bx + ax * bw + ay * bz - az * by,
        aw * by - ax * bz + ay * bw + az * bx,
        aw * bz + ax * by - ay * bx + az * bw);

    // q_samp = normalize((nz - 0.5) * [1, .05, .05, .05])
    float sw = nz.x - 0.5f;
    float sx = (nz.y - 0.5f) * 0.05f;
    float sy = (nz.z - 0.5f) * 0.05f;
    float sz = (nz.w - 0.5f) * 0.05f;
    float d = sw * sw + sx * sx + sy * sy + sz * sz;
    float r = rsqrtf(d);
    r = r * (1.5f - 0.5f * d * r * r);   // one Newton step -> full fp32 accuracy
    float4 samp = make_float4(sw * r, sx * r, sy * r, sz * r);

    return qmul(rel, samp);
}

// Pass 1: per (chunk c, column n), product of q_dot over the chunk (newest left).
__global__ void __launch_bounds__(BLK) pass1_totals(
    const float4* __restrict__ q, const float4* __restrict__ noise,
    int NS, int T, int L)
{
    int n = blockIdx.x * BLK + threadIdx.x;
    if (n >= NS) return;
    int c = blockIdx.y;
    int t0 = c * L;
    int t1 = min(T, t0 + L);
    float4 acc = make_float4(1.f, 0.f, 0.f, 0.f);
    if (t0 < T) {
        float4 qprev = q[(size_t)t0 * NS + n];
        #pragma unroll 4
        for (int t = t0; t < t1; ++t) {
            float4 qn = q[(size_t)(t + 1) * NS + n];
            float4 nz = noise[(size_t)t * NS + n];
            acc = qmul(qdot_step(qn, qprev, nz), acc);
            qprev = qn;
        }
    }
    g_totals[c * NS + n] = acc;
}

// Pass 2: per column, exclusive scan of chunk totals seeded with q[0].
// Also writes output row 0.
__global__ void __launch_bounds__(BLK) pass2_scan(
    const float4* __restrict__ q, float4* __restrict__ out, int NS)
{
    int n = blockIdx.x * BLK + threadIdx.x;
    if (n >= NS) return;
    float4 carry = q[n];      // q[0][n]
    out[n] = carry;           // out[0] = q[0]
    #pragma unroll 4
    for (int c = 0; c < NCH; ++c) {
        g_carry[c * NS + n] = carry;
        carry = qmul(g_totals[c * NS + n], carry);
    }
}

// Pass 3: per (chunk, column), re-walk chunk applying carry, write out rows t+1.
__global__ void __launch_bounds__(BLK) pass3_apply(
    const float4* __restrict__ q, const float4* __restrict__ noise,
    float4* __restrict__ out, int NS, int T, int L)
{
    int n = blockIdx.x * BLK + threadIdx.x;
    if (n >= NS) return;
    int c = blockIdx.y;
    int t0 = c * L;
    int t1 = min(T, t0 + L);
    if (t0 >= T) return;
    float4 acc = g_carry[c * NS + n];
    float4 qprev = q[(size_t)t0 * NS + n];
    #pragma unroll 4
    for (int t = t0; t < t1; ++t) {
        float4 qn = q[(size_t)(t + 1) * NS + n];
        float4 nz = noise[(size_t)t * NS + n];
        acc = qmul(qdot_step(qn, qprev, nz), acc);
        out[(size_t)(t + 1) * NS + n] = acc;
        qprev = qn;
    }
}

extern "C" void kernel_launch(void* const* d_in, const int* in_sizes, int n_in,
                              void* d_out, int out_size)
{
    const float4* q     = (const float4*)d_in[0];
    const float4* noise = (const float4*)d_in[1];
    float4* out         = (float4*)d_out;

    // Derive shapes: in_sizes[0] = TS*NS*4, in_sizes[1] = (TS-1)*NS*4
    int quats0 = in_sizes[0] / 4;          // TS*NS
    int quats1 = in_sizes[1] / 4;          // (TS-1)*NS
    int NS = quats0 - quats1;              // columns
    int TS = quats0 / NS;                  // timesteps
    int T  = TS - 1;                       // q_dot length
    int L  = (T + NCH - 1) / NCH;          // chunk length

    dim3 grid_cols((NS + BLK - 1) / BLK);
    dim3 grid_ct(grid_cols.x, NCH);

    pass1_totals<<<grid_ct, BLK>>>(q, noise, NS, T, L);
    pass2_scan  <<<grid_cols, BLK>>>(q, out, NS);
    pass3_apply <<<grid_ct, BLK>>>(q, noise, out, NS, T, L);
}